// round 4
// baseline (speedup 1.0000x reference)
#include <cuda_runtime.h>
#include <cuda_fp16.h>
#include <math.h>

#define NN 50000
#define EE 800000
#define INC 128
#define HIDC 64
#define NHEADS 4
#define NG 64
#define NCLS 10
#define BN_EPS 1e-5f

typedef unsigned int uint;

// ---------------- scratch (static device globals) ---------------------------
__device__ __align__(16) __half g_hh[NN * 256];   // fp16 transformed feats (pre-bias)
__device__ __align__(16) float g_agg[NN * 256];   // aggregation output / layer input
__device__ float g_as[NN * NHEADS];
__device__ float g_ad[NN * NHEADS];
__device__ int   g_rp[NN + 1];                    // CSR row ptr (by dst)
__device__ int   g_cur[NN];                       // degree counter / fill cursor
__device__ int   g_col[EE];                       // CSR: src node per slot
__device__ float g_bn[2 * 256];
__device__ float g_scl[256];
__device__ float g_sh[256];
__device__ float g_pool[NG * HIDC];
__device__ float g_cnt[NG];

static inline int ceil_div(int a, int b) { return (a + b - 1) / b; }

// ---------------- zero kernels ----------------------------------------------
__global__ void zero_f_k(float* p, int n) {
    int i = blockIdx.x * blockDim.x + threadIdx.x;
    if (i < n) p[i] = 0.f;
}
__global__ void zero_i_k(int* p, int n) {
    int i = blockIdx.x * blockDim.x + threadIdx.x;
    if (i < n) p[i] = 0;
}

// ---------------- CSR build --------------------------------------------------
__global__ void count_k(const int* __restrict__ dst) {
    int e = blockIdx.x * blockDim.x + threadIdx.x;
    if (e < EE) atomicAdd(&g_cur[dst[e]], 1);
}

#define SCAN_T 512
__global__ void scan_k() {
    __shared__ int sh[SCAN_T];
    int t = threadIdx.x;
    int chunk = (NN + SCAN_T - 1) / SCAN_T;
    int base = t * chunk;
    int s = 0;
    for (int j = 0; j < chunk; j++) {
        int idx = base + j;
        if (idx < NN) s += g_cur[idx];
    }
    sh[t] = s;
    __syncthreads();
    for (int off = 1; off < SCAN_T; off <<= 1) {
        int v = (t >= off) ? sh[t - off] : 0;
        __syncthreads();
        sh[t] += v;
        __syncthreads();
    }
    int running = sh[t] - s;  // exclusive prefix
    for (int j = 0; j < chunk; j++) {
        int idx = base + j;
        if (idx < NN) {
            int d = g_cur[idx];
            g_rp[idx] = running;
            g_cur[idx] = running;
            running += d;
        }
    }
    if (t == SCAN_T - 1) g_rp[NN] = sh[SCAN_T - 1];
}

__global__ void fill_k(const int* __restrict__ src, const int* __restrict__ dst) {
    int e = blockIdx.x * blockDim.x + threadIdx.x;
    if (e >= EE) return;
    int p = atomicAdd(&g_cur[dst[e]], 1);
    g_col[p] = src[e];
}

// ---------------- 3xTF32 tensor-core GEMM + fused logits + fp16 out ---------
#define BM 128
#define BN 64
#define BK 32
#define SAS (BK + 4)
#define SBS (BN + 8)

__device__ __forceinline__ uint f2tf32(float x) {
    uint r;
    asm("cvt.rna.tf32.f32 %0, %1;" : "=r"(r) : "f"(x));
    return r;
}
__device__ __forceinline__ void mma8(float* c, const uint* a, const uint* b) {
    asm volatile(
        "mma.sync.aligned.m16n8k8.row.col.f32.tf32.tf32.f32 "
        "{%0,%1,%2,%3}, {%4,%5,%6,%7}, {%8,%9}, {%0,%1,%2,%3};"
        : "+f"(c[0]), "+f"(c[1]), "+f"(c[2]), "+f"(c[3])
        : "r"(a[0]), "r"(a[1]), "r"(a[2]), "r"(a[3]), "r"(b[0]), "r"(b[1]));
}

// C = A' @ B; A' = A*scl+sh (prev-layer BN). Emits fp16 h, plus as/ad logits.
__global__ void __launch_bounds__(256) tgemm_k(const float* __restrict__ A,
                                               const float* __restrict__ B,
                                               const float* __restrict__ asrc,
                                               const float* __restrict__ adst,
                                               int n, int K, int M, int H,
                                               int useBN) {
    __shared__ float sA[BM][SAS];
    __shared__ float sB[BK][SBS];
    __shared__ float sAs[BM];
    __shared__ float sAd[BM];
    int tid = threadIdx.x;
    int lane = tid & 31;
    int wid = tid >> 5;
    int warpM = wid >> 1, warpN = wid & 1;
    int gid = lane >> 2, tq = lane & 3;
    int row0 = blockIdx.x * BM, col0 = blockIdx.y * BN;
    int hd = blockIdx.y;  // head index (BN == HIDC)

    int a_r = tid >> 3, a_q4 = (tid & 7) * 4;
    int b_kr = tid >> 4, b_nc4 = (tid & 15) * 4;

    float4 pa[4];
    float4 pb[2];

    auto loadTiles = [&](int k0) {
        float scl0 = 1.f, scl1 = 1.f, scl2 = 1.f, scl3 = 1.f;
        float sh0 = 0.f, sh1 = 0.f, sh2 = 0.f, sh3 = 0.f;
        if (useBN) {
            scl0 = g_scl[k0 + a_q4 + 0]; sh0 = g_sh[k0 + a_q4 + 0];
            scl1 = g_scl[k0 + a_q4 + 1]; sh1 = g_sh[k0 + a_q4 + 1];
            scl2 = g_scl[k0 + a_q4 + 2]; sh2 = g_sh[k0 + a_q4 + 2];
            scl3 = g_scl[k0 + a_q4 + 3]; sh3 = g_sh[k0 + a_q4 + 3];
        }
#pragma unroll
        for (int i = 0; i < 4; i++) {
            int gr = row0 + i * 32 + a_r;
            float4 v = make_float4(0.f, 0.f, 0.f, 0.f);
            if (gr < n) v = *(const float4*)&A[(size_t)gr * K + k0 + a_q4];
            if (useBN) {
                v.x = v.x * scl0 + sh0;
                v.y = v.y * scl1 + sh1;
                v.z = v.z * scl2 + sh2;
                v.w = v.w * scl3 + sh3;
            }
            pa[i] = v;
        }
#pragma unroll
        for (int i = 0; i < 2; i++) {
            int kr = k0 + i * 16 + b_kr;
            pb[i] = *(const float4*)&B[(size_t)kr * M + col0 + b_nc4];
        }
    };
    auto storeTiles = [&]() {
#pragma unroll
        for (int i = 0; i < 4; i++)
            *(float4*)&sA[i * 32 + a_r][a_q4] = pa[i];
#pragma unroll
        for (int i = 0; i < 2; i++)
            *(float4*)&sB[i * 16 + b_kr][b_nc4] = pb[i];
    };

    float c[2][4][4];
#pragma unroll
    for (int mt = 0; mt < 2; mt++)
#pragma unroll
        for (int nt = 0; nt < 4; nt++)
#pragma unroll
            for (int j = 0; j < 4; j++) c[mt][nt][j] = 0.f;

    int nk = K / BK;
    loadTiles(0);
    for (int it = 0; it < nk; it++) {
        storeTiles();
        __syncthreads();
        if (it + 1 < nk) loadTiles((it + 1) * BK);
#pragma unroll
        for (int ks = 0; ks < 4; ks++) {
            int k = ks * 8;
            float af[2][4], bf[4][2];
#pragma unroll
            for (int mt = 0; mt < 2; mt++) {
                int m = warpM * 32 + mt * 16;
                af[mt][0] = sA[m + gid][k + tq];
                af[mt][1] = sA[m + gid + 8][k + tq];
                af[mt][2] = sA[m + gid][k + tq + 4];
                af[mt][3] = sA[m + gid + 8][k + tq + 4];
            }
#pragma unroll
            for (int nt = 0; nt < 4; nt++) {
                int nb = warpN * 32 + nt * 8;
                bf[nt][0] = sB[k + tq][nb + gid];
                bf[nt][1] = sB[k + tq + 4][nb + gid];
            }
            uint ah[2][4], al[2][4], bh[4][2], bl[4][2];
#pragma unroll
            for (int mt = 0; mt < 2; mt++)
#pragma unroll
                for (int j = 0; j < 4; j++) {
                    uint hi = f2tf32(af[mt][j]);
                    ah[mt][j] = hi;
                    al[mt][j] = f2tf32(af[mt][j] - __uint_as_float(hi));
                }
#pragma unroll
            for (int nt = 0; nt < 4; nt++)
#pragma unroll
                for (int j = 0; j < 2; j++) {
                    uint hi = f2tf32(bf[nt][j]);
                    bh[nt][j] = hi;
                    bl[nt][j] = f2tf32(bf[nt][j] - __uint_as_float(hi));
                }
#pragma unroll
            for (int mt = 0; mt < 2; mt++)
#pragma unroll
                for (int nt = 0; nt < 4; nt++) {
                    mma8(c[mt][nt], ah[mt], bh[nt]);
                    mma8(c[mt][nt], al[mt], bh[nt]);
                    mma8(c[mt][nt], ah[mt], bl[nt]);
                }
        }
        __syncthreads();
    }

    // ---- epilogue: fp16 h store + fused attention logits ----
    // zero logit accumulators
    if (tid < BM) { sAs[tid] = 0.f; sAd[tid] = 0.f; }
    __syncthreads();

    float pAs[4] = {0.f, 0.f, 0.f, 0.f};
    float pAd[4] = {0.f, 0.f, 0.f, 0.f};
#pragma unroll
    for (int nt = 0; nt < 4; nt++) {
        int cc = warpN * 32 + nt * 8 + tq * 2;  // col within head
        float a0 = __ldg(&asrc[hd * HIDC + cc]);
        float a1 = __ldg(&asrc[hd * HIDC + cc + 1]);
        float d0 = __ldg(&adst[hd * HIDC + cc]);
        float d1 = __ldg(&adst[hd * HIDC + cc + 1]);
#pragma unroll
        for (int mt = 0; mt < 2; mt++) {
            pAs[mt * 2 + 0] += c[mt][nt][0] * a0 + c[mt][nt][1] * a1;
            pAs[mt * 2 + 1] += c[mt][nt][2] * a0 + c[mt][nt][3] * a1;
            pAd[mt * 2 + 0] += c[mt][nt][0] * d0 + c[mt][nt][1] * d1;
            pAd[mt * 2 + 1] += c[mt][nt][2] * d0 + c[mt][nt][3] * d1;
        }
        // fp16 h store
#pragma unroll
        for (int mt = 0; mt < 2; mt++) {
            int r0g = row0 + warpM * 32 + mt * 16 + gid;
            int r1g = r0g + 8;
            int gc = col0 + cc;
            if (r0g < n)
                *(half2*)&g_hh[(size_t)r0g * M + gc] =
                    __floats2half2_rn(c[mt][nt][0], c[mt][nt][1]);
            if (r1g < n)
                *(half2*)&g_hh[(size_t)r1g * M + gc] =
                    __floats2half2_rn(c[mt][nt][2], c[mt][nt][3]);
        }
    }
    // reduce over tq lanes (lane bits 0,1)
#pragma unroll
    for (int j = 0; j < 4; j++) {
        pAs[j] += __shfl_xor_sync(0xffffffffu, pAs[j], 1);
        pAs[j] += __shfl_xor_sync(0xffffffffu, pAs[j], 2);
        pAd[j] += __shfl_xor_sync(0xffffffffu, pAd[j], 1);
        pAd[j] += __shfl_xor_sync(0xffffffffu, pAd[j], 2);
    }
    if (tq == 0) {
#pragma unroll
        for (int mt = 0; mt < 2; mt++)
#pragma unroll
            for (int p = 0; p < 2; p++) {
                int lr = warpM * 32 + mt * 16 + p * 8 + gid;
                atomicAdd(&sAs[lr], pAs[mt * 2 + p]);
                atomicAdd(&sAd[lr], pAd[mt * 2 + p]);
            }
    }
    __syncthreads();
    if (tid < BM) {
        int r = row0 + tid;
        if (r < n) {
            g_as[r * H + hd] = sAs[tid];
            g_ad[r * H + hd] = sAd[tid];
        }
    }
}

// ---------------- gather aggregation, H=4 (warp per dst node) ---------------
__global__ void agg4_k(const float* __restrict__ bias) {
    int warp = (blockIdx.x * blockDim.x + threadIdx.x) >> 5;
    int lane = threadIdx.x & 31;
    if (warp >= NN) return;
    int node = warp;
    int hs = lane >> 3;  // head owning my 8 channels
    float ad_h = (lane < 4) ? g_ad[node * 4 + lane] : 0.f;
    float den = 0.f;
    float acc[8] = {0.f, 0.f, 0.f, 0.f, 0.f, 0.f, 0.f, 0.f};
    int beg = g_rp[node], end = g_rp[node + 1];
    int j = beg;
    for (; j + 1 < end; j += 2) {
        int s0 = __ldg(&g_col[j]);
        int s1 = __ldg(&g_col[j + 1]);
        float e0 = 0.f, e1 = 0.f;
        if (lane < 4) {
            float v0 = __ldg(&g_as[s0 * 4 + lane]) + ad_h;
            float v1 = __ldg(&g_as[s1 * 4 + lane]) + ad_h;
            v0 = (v0 > 0.f) ? v0 : 0.2f * v0;
            v1 = (v1 > 0.f) ? v1 : 0.2f * v1;
            e0 = __expf(v0);
            e1 = __expf(v1);
            den += e0 + e1;
        }
        uint4 u0 = __ldg((const uint4*)&g_hh[(size_t)s0 * 256 + lane * 8]);
        uint4 u1 = __ldg((const uint4*)&g_hh[(size_t)s1 * 256 + lane * 8]);
        float ex0 = __shfl_sync(0xffffffffu, e0, hs);
        float ex1 = __shfl_sync(0xffffffffu, e1, hs);
        float2 f;
        f = __half22float2(*(half2*)&u0.x); acc[0] += ex0 * f.x; acc[1] += ex0 * f.y;
        f = __half22float2(*(half2*)&u0.y); acc[2] += ex0 * f.x; acc[3] += ex0 * f.y;
        f = __half22float2(*(half2*)&u0.z); acc[4] += ex0 * f.x; acc[5] += ex0 * f.y;
        f = __half22float2(*(half2*)&u0.w); acc[6] += ex0 * f.x; acc[7] += ex0 * f.y;
        f = __half22float2(*(half2*)&u1.x); acc[0] += ex1 * f.x; acc[1] += ex1 * f.y;
        f = __half22float2(*(half2*)&u1.y); acc[2] += ex1 * f.x; acc[3] += ex1 * f.y;
        f = __half22float2(*(half2*)&u1.z); acc[4] += ex1 * f.x; acc[5] += ex1 * f.y;
        f = __half22float2(*(half2*)&u1.w); acc[6] += ex1 * f.x; acc[7] += ex1 * f.y;
    }
    if (j < end) {
        int s0 = __ldg(&g_col[j]);
        float e0 = 0.f;
        if (lane < 4) {
            float v0 = __ldg(&g_as[s0 * 4 + lane]) + ad_h;
            v0 = (v0 > 0.f) ? v0 : 0.2f * v0;
            e0 = __expf(v0);
            den += e0;
        }
        uint4 u0 = __ldg((const uint4*)&g_hh[(size_t)s0 * 256 + lane * 8]);
        float ex0 = __shfl_sync(0xffffffffu, e0, hs);
        float2 f;
        f = __half22float2(*(half2*)&u0.x); acc[0] += ex0 * f.x; acc[1] += ex0 * f.y;
        f = __half22float2(*(half2*)&u0.y); acc[2] += ex0 * f.x; acc[3] += ex0 * f.y;
        f = __half22float2(*(half2*)&u0.z); acc[4] += ex0 * f.x; acc[5] += ex0 * f.y;
        f = __half22float2(*(half2*)&u0.w); acc[6] += ex0 * f.x; acc[7] += ex0 * f.y;
    }
    float denh = __shfl_sync(0xffffffffu, den, hs);
    float inv = (denh > 0.f) ? 1.f / denh : 0.f;
    float4 b0 = __ldg(&((const float4*)bias)[lane * 2]);
    float4 b1 = __ldg(&((const float4*)bias)[lane * 2 + 1]);
    float4 o0, o1;
    o0.x = fmaxf(acc[0] * inv + b0.x, 0.f);
    o0.y = fmaxf(acc[1] * inv + b0.y, 0.f);
    o0.z = fmaxf(acc[2] * inv + b0.z, 0.f);
    o0.w = fmaxf(acc[3] * inv + b0.w, 0.f);
    o1.x = fmaxf(acc[4] * inv + b1.x, 0.f);
    o1.y = fmaxf(acc[5] * inv + b1.y, 0.f);
    o1.z = fmaxf(acc[6] * inv + b1.z, 0.f);
    o1.w = fmaxf(acc[7] * inv + b1.w, 0.f);
    float* op = g_agg + (size_t)node * 256 + lane * 8;
    *(float4*)op = o0;
    *(float4*)(op + 4) = o1;
}

// ---------------- gather aggregation, H=1 -----------------------------------
__global__ void agg1_k(const float* __restrict__ bias) {
    int warp = (blockIdx.x * blockDim.x + threadIdx.x) >> 5;
    int lane = threadIdx.x & 31;
    if (warp >= NN) return;
    int node = warp;
    float ad0 = g_ad[node];
    float den = 0.f;
    float accx = 0.f, accy = 0.f;
    int beg = g_rp[node], end = g_rp[node + 1];
    int j = beg;
    for (; j + 1 < end; j += 2) {
        int s0 = __ldg(&g_col[j]);
        int s1 = __ldg(&g_col[j + 1]);
        float e0 = 0.f, e1 = 0.f;
        if (lane == 0) {
            float v0 = __ldg(&g_as[s0]) + ad0;
            float v1 = __ldg(&g_as[s1]) + ad0;
            v0 = (v0 > 0.f) ? v0 : 0.2f * v0;
            v1 = (v1 > 0.f) ? v1 : 0.2f * v1;
            e0 = __expf(v0);
            e1 = __expf(v1);
            den += e0 + e1;
        }
        uint u0 = __ldg((const uint*)&g_hh[(size_t)s0 * 64 + lane * 2]);
        uint u1 = __ldg((const uint*)&g_hh[(size_t)s1 * 64 + lane * 2]);
        e0 = __shfl_sync(0xffffffffu, e0, 0);
        e1 = __shfl_sync(0xffffffffu, e1, 0);
        float2 f0 = __half22float2(*(half2*)&u0);
        float2 f1 = __half22float2(*(half2*)&u1);
        accx += e0 * f0.x + e1 * f1.x;
        accy += e0 * f0.y + e1 * f1.y;
    }
    if (j < end) {
        int s0 = __ldg(&g_col[j]);
        float e0 = 0.f;
        if (lane == 0) {
            float v0 = __ldg(&g_as[s0]) + ad0;
            v0 = (v0 > 0.f) ? v0 : 0.2f * v0;
            e0 = __expf(v0);
            den += e0;
        }
        uint u0 = __ldg((const uint*)&g_hh[(size_t)s0 * 64 + lane * 2]);
        e0 = __shfl_sync(0xffffffffu, e0, 0);
        float2 f0 = __half22float2(*(half2*)&u0);
        accx += e0 * f0.x;
        accy += e0 * f0.y;
    }
    den = __shfl_sync(0xffffffffu, den, 0);
    float inv = (den > 0.f) ? 1.f / den : 0.f;
    float2 b = __ldg(&((const float2*)bias)[lane]);
    float2 o;
    o.x = fmaxf(accx * inv + b.x, 0.f);
    o.y = fmaxf(accy * inv + b.y, 0.f);
    *(float2*)(g_agg + (size_t)node * 64 + lane * 2) = o;
}

// ---------------- BN stats ----------------------------------------------------
__global__ void stats_k(const float* __restrict__ y, int n, int HC, int rowsPer) {
    int c = threadIdx.x;
    int r0 = blockIdx.x * rowsPer;
    int r1 = min(r0 + rowsPer, n);
    float s = 0.f, ss = 0.f;
    for (int r = r0; r < r1; r++) {
        float v = y[(size_t)r * HC + c];
        s += v;
        ss += v * v;
    }
    atomicAdd(&g_bn[c], s);
    atomicAdd(&g_bn[HC + c], ss);
}

__global__ void mkbn_k(const float* __restrict__ gam, const float* __restrict__ bet,
                       int HC, int n) {
    int c = threadIdx.x;
    if (c >= HC) return;
    float inv_n = 1.f / (float)n;
    float mean = g_bn[c] * inv_n;
    float var = g_bn[HC + c] * inv_n - mean * mean;
    float s = rsqrtf(var + BN_EPS) * gam[c];
    g_scl[c] = s;
    g_sh[c] = bet[c] - mean * s;
}

// ---------------- pool + FC ---------------------------------------------------
__global__ void cnt_k(const int* __restrict__ batch) {
    int n = blockIdx.x * blockDim.x + threadIdx.x;
    if (n < NN) atomicAdd(&g_cnt[batch[n]], 1.f);
}
__global__ void pool_k(const float* __restrict__ h, const int* __restrict__ batch) {
    int idx = blockIdx.x * blockDim.x + threadIdx.x;
    if (idx >= NN * HIDC) return;
    int n = idx / HIDC, c = idx - n * HIDC;
    int g = batch[n];
    float v = h[idx] * g_scl[c] + g_sh[c];
    atomicAdd(&g_pool[g * HIDC + c], v);
}
__global__ void fc_k(const float* __restrict__ fcW, const float* __restrict__ fcb,
                     float* __restrict__ out) {
    int idx = threadIdx.x;
    if (idx >= NG * NCLS) return;
    int g = idx / NCLS, c = idx - g * NCLS;
    float cnt = fmaxf(g_cnt[g], 1.0f);
    float inv = 1.0f / cnt;
    float s = fcb[c];
#pragma unroll
    for (int k = 0; k < HIDC; k++)
        s += (g_pool[g * HIDC + k] * inv) * fcW[k * NCLS + c];
    out[idx] = s;
}

// ---------------- host orchestration ----------------------------------------
extern "C" void kernel_launch(void* const* d_in, const int* in_sizes, int n_in,
                              void* d_out, int out_size) {
    const float* x   = (const float*)d_in[0];
    const int* ei    = (const int*)d_in[1];
    const int* batch = (const int*)d_in[2];
    const float* W1  = (const float*)d_in[3];
    const float* as1 = (const float*)d_in[4];
    const float* ad1 = (const float*)d_in[5];
    const float* b1  = (const float*)d_in[6];
    const float* g1  = (const float*)d_in[7];
    const float* be1 = (const float*)d_in[8];
    const float* W2  = (const float*)d_in[9];
    const float* as2 = (const float*)d_in[10];
    const float* ad2 = (const float*)d_in[11];
    const float* b2  = (const float*)d_in[12];
    const float* g2  = (const float*)d_in[13];
    const float* be2 = (const float*)d_in[14];
    const float* W3  = (const float*)d_in[15];
    const float* as3 = (const float*)d_in[16];
    const float* ad3 = (const float*)d_in[17];
    const float* b3  = (const float*)d_in[18];
    const float* g3  = (const float*)d_in[19];
    const float* be3 = (const float*)d_in[20];
    const float* fcW = (const float*)d_in[21];
    const float* fcb = (const float*)d_in[22];
    const int* src = ei;
    const int* dst = ei + EE;

    float *aggbuf, *bnbuf, *poolbuf, *cntbuf;
    int* curbuf;
    cudaGetSymbolAddress((void**)&aggbuf, g_agg);
    cudaGetSymbolAddress((void**)&bnbuf, g_bn);
    cudaGetSymbolAddress((void**)&poolbuf, g_pool);
    cudaGetSymbolAddress((void**)&cntbuf, g_cnt);
    cudaGetSymbolAddress((void**)&curbuf, g_cur);

    // ---- build CSR (dst -> list of src) ----
    zero_i_k<<<ceil_div(NN, 256), 256>>>(curbuf, NN);
    count_k<<<ceil_div(EE, 256), 256>>>(dst);
    scan_k<<<1, SCAN_T>>>();
    fill_k<<<ceil_div(EE, 256), 256>>>(src, dst);

    auto run_layer = [&](const float* in, int K, const float* W, const float* asv,
                         const float* adv, const float* b, const float* gam,
                         const float* bet, int H, int useBN) {
        int HC = H * HIDC;
        dim3 gg(ceil_div(NN, BM), HC / BN);
        tgemm_k<<<gg, 256>>>(in, W, asv, adv, NN, K, HC, H, useBN);
        if (H == 4)
            agg4_k<<<ceil_div(NN * 32, 256), 256>>>(b);
        else
            agg1_k<<<ceil_div(NN * 32, 256), 256>>>(b);
        zero_f_k<<<2, 256>>>(bnbuf, 2 * HC);
        stats_k<<<512, HC>>>(aggbuf, NN, HC, ceil_div(NN, 512));
        mkbn_k<<<1, 256>>>(gam, bet, HC, NN);
    };

    run_layer(x,      INC, W1, as1, ad1, b1, g1, be1, NHEADS, 0);
    run_layer(aggbuf, 256, W2, as2, ad2, b2, g2, be2, NHEADS, 1);
    run_layer(aggbuf, 256, W3, as3, ad3, b3, g3, be3, 1, 1);

    // ---- global mean pool (applies layer-3 BN inline) + FC ----
    zero_f_k<<<ceil_div(NG * HIDC, 256), 256>>>(poolbuf, NG * HIDC);
    zero_f_k<<<1, NG>>>(cntbuf, NG);
    cnt_k<<<ceil_div(NN, 256), 256>>>(batch);
    pool_k<<<ceil_div(NN * HIDC, 256), 256>>>(aggbuf, batch);
    fc_k<<<1, 640>>>(fcW, fcb, (float*)d_out);
}